// round 7
// baseline (speedup 1.0000x reference)
#include <cuda_runtime.h>
#include <cuda_fp16.h>
#include <math.h>

#define NB 2
#define NH 64
#define NW 64
#define NC 256
#define NQ 4096
#define NK 49
#define NLEV 4
#define QPB 16
#define NBINS 256

// Packed pyramid scratch (levels 1..3, un-normalized fp32) and fp16 normalized.
#define PYR_PX (NB * (32*32 + 16*16 + 8*8))
__device__ float  g_pyrA[PYR_PX * NC];
__device__ __half g_h0[NB*64*64*NC];
__device__ __half g_hA[PYR_PX * NC];
__device__ int    g_perm[NB*NQ];   // sorted slot -> packed query index (b*NQ+n)

#define OFF_L1 0
#define OFF_L2 (NB * 32 * 32)
#define OFF_L3 (NB * (32*32 + 16*16))

__device__ __forceinline__ unsigned int h2_as_u32(__half2 h) {
    return *reinterpret_cast<unsigned int*>(&h);
}

// ---------------- Counting sort of queries by level-0 4x4 cell ----------------
__global__ void __launch_bounds__(1024) sort_kernel(const float* __restrict__ coords2) {
    __shared__ int cnt[NB*NBINS];
    __shared__ int sc[NB*NBINS];
    __shared__ int cur[NB*NBINS];
    int tid = threadIdx.x;
    if (tid < NB*NBINS) cnt[tid] = 0;
    __syncthreads();
    int mybin[8];
    int myidx[8];
#pragma unroll
    for (int k = 0; k < 8; k++) {
        int i = tid + k * 1024;          // i = b*NQ + n
        int b = i >> 12;
        float qx = coords2[(size_t)i * 2 + 0];
        float qy = coords2[(size_t)i * 2 + 1];
        int ix = min(max((int)floorf(qx), 0), 63);
        int iy = min(max((int)floorf(qy), 0), 63);
        int bin = b * NBINS + ((iy >> 2) << 4) + (ix >> 2);
        mybin[k] = bin;
        myidx[k] = i;
        atomicAdd(&cnt[bin], 1);
    }
    __syncthreads();
    if (tid < NB*NBINS) sc[tid] = cnt[tid];
    __syncthreads();
    for (int off = 1; off < NB*NBINS; off <<= 1) {
        int v = 0;
        if (tid < NB*NBINS && tid >= off) v = sc[tid - off];
        __syncthreads();
        if (tid < NB*NBINS) sc[tid] += v;
        __syncthreads();
    }
    if (tid < NB*NBINS) cur[tid] = sc[tid] - cnt[tid];   // exclusive
    __syncthreads();
#pragma unroll
    for (int k = 0; k < 8; k++) {
        int slot = atomicAdd(&cur[mybin[k]], 1);
        g_perm[slot] = myidx[k];
    }
}

// jax.image.resize(method='bilinear', antialias=True) 2x downsample taps.
__device__ __forceinline__ void resize_taps(int i, int n, int jj[4], float ww[4]) {
    float c = 2.0f * (float)i + 0.5f;
    float s = 0.0f;
#pragma unroll
    for (int t = 0; t < 4; t++) {
        int j = 2 * i - 1 + t;
        float w = 0.0f;
        if (j >= 0 && j < n) w = 1.0f - 0.5f * fabsf(c - (float)j);
        jj[t] = j < 0 ? 0 : (j > n - 1 ? n - 1 : j);
        ww[t] = w;
        s += w;
    }
    float inv = 1.0f / s;
#pragma unroll
    for (int t = 0; t < 4; t++) ww[t] *= inv;
}

__global__ void downsample_kernel(const float* __restrict__ in, float* __restrict__ out,
                                  int Hi, int Wi) {
    int Ho = Hi >> 1, Wo = Wi >> 1;
    int p = blockIdx.x;
    int b = blockIdx.y;
    int yo = p / Wo, xo = p % Wo;
    int c = threadIdx.x;
    int jy[4], jx[4];
    float wy[4], wx[4];
    resize_taps(yo, Hi, jy, wy);
    resize_taps(xo, Wi, jx, wx);
    const float* ib = in + (size_t)b * Hi * Wi * NC;
    float acc = 0.0f;
#pragma unroll
    for (int a = 0; a < 4; a++) {
        float r = 0.0f;
#pragma unroll
        for (int t = 0; t < 4; t++)
            r += wx[t] * ib[((size_t)jy[a] * Wi + jx[t]) * NC + c];
        acc += wy[a] * r;
    }
    out[(((size_t)b * Ho + yo) * Wo + xo) * NC + c] = acc;
}

// Warp-per-pixel L2 normalize, fp32 in -> fp16 out; handles h0 region then hA region.
__global__ void __launch_bounds__(256) normalize_all_kernel(
    const float* __restrict__ in0, __half* __restrict__ out0,
    const float* __restrict__ inA, __half* __restrict__ outA) {
    int warp = threadIdx.x >> 5, lane = threadIdx.x & 31;
    int p = blockIdx.x * 8 + warp;
    const float* in;
    __half* out;
    if (p < NB * 64 * 64) { in = in0; out = out0; }
    else { in = inA; out = outA; p -= NB * 64 * 64; }
    size_t base = (size_t)p * NC;
    const float4* ip = (const float4*)(in + base);
    float4 a0 = ip[lane * 2];
    float4 a1 = ip[lane * 2 + 1];
    float s = a0.x*a0.x + a0.y*a0.y + a0.z*a0.z + a0.w*a0.w +
              a1.x*a1.x + a1.y*a1.y + a1.z*a1.z + a1.w*a1.w;
#pragma unroll
    for (int o = 16; o > 0; o >>= 1) s += __shfl_xor_sync(0xffffffffu, s, o);
    float inv = 1.0f / (sqrtf(s) + 1e-6f);
    __half2 h0 = __floats2half2_rn(a0.x * inv, a0.y * inv);
    __half2 h1 = __floats2half2_rn(a0.z * inv, a0.w * inv);
    __half2 h2 = __floats2half2_rn(a1.x * inv, a1.y * inv);
    __half2 h3 = __floats2half2_rn(a1.z * inv, a1.w * inv);
    uint4 pk;
    pk.x = h2_as_u32(h0); pk.y = h2_as_u32(h1);
    pk.z = h2_as_u32(h2); pk.w = h2_as_u32(h3);
    ((uint4*)(out + base))[lane] = pk;
}

// Main kernel: one block per 16 spatially-binned queries. 256 threads.
__global__ void __launch_bounds__(256) corr_kernel(
    const float* __restrict__ fmap1,
    const float* __restrict__ coords1,
    const float* __restrict__ coords2,
    const __half* __restrict__ h0,
    const __half* __restrict__ hA,
    float* __restrict__ out) {
    int tid = threadIdx.x;
    int lane = tid & 31, wid = tid >> 5;

    __shared__ float feat1s[QPB][NC];        // 16 KB
    __shared__ float Ds[QPB][NLEV * 64];     // 16 KB
    __shared__ float qx_s[QPB], qy_s[QPB];
    __shared__ int   qn_s[QPB];

    if (tid < QPB) {
        int p = g_perm[blockIdx.x * QPB + tid];
        qn_s[tid] = p;
        qx_s[tid] = coords2[(size_t)p * 2 + 0];
        qy_s[tid] = coords2[(size_t)p * 2 + 1];
    }
    __syncthreads();

    // ---- Stage A: feat1 per query, warp-per-query (2 rounds), no block syncs ----
#pragma unroll
    for (int r = 0; r < 2; r++) {
        int qi = r * 8 + wid;
        int p = qn_s[qi];
        int b = p >> 12;
        float cx = __ldg(&coords1[(size_t)p * 2 + 0]);
        float cy = __ldg(&coords1[(size_t)p * 2 + 1]);
        int fx0 = (int)floorf(cx);
        int fy0 = (int)floorf(cy);
        int x0 = min(max(fx0, 0), NW - 1);
        int x1 = min(max(fx0 + 1, 0), NW - 1);
        int y0 = min(max(fy0, 0), NH - 1);
        int y1 = min(max(fy0 + 1, 0), NH - 1);
        float wa = ((float)x1 - cx) * ((float)y1 - cy);
        float wb = ((float)x1 - cx) * (cy - (float)y0);
        float wc = (cx - (float)x0) * ((float)y1 - cy);
        float wd = (cx - (float)x0) * (cy - (float)y0);
        const float* fb1 = fmap1 + (size_t)b * NH * NW * NC;
        int c0 = lane * 8;
        const float4* pa = (const float4*)(fb1 + ((size_t)y0 * NW + x0) * NC + c0);
        const float4* pb = (const float4*)(fb1 + ((size_t)y1 * NW + x0) * NC + c0);
        const float4* pc = (const float4*)(fb1 + ((size_t)y0 * NW + x1) * NC + c0);
        const float4* pd = (const float4*)(fb1 + ((size_t)y1 * NW + x1) * NC + c0);
        float v[8];
#pragma unroll
        for (int h = 0; h < 2; h++) {
            float4 A = __ldcg(pa + h), Bv = __ldcg(pb + h), Cv = __ldcg(pc + h), Dv = __ldcg(pd + h);
            v[h*4+0] = wa*A.x + wb*Bv.x + wc*Cv.x + wd*Dv.x;
            v[h*4+1] = wa*A.y + wb*Bv.y + wc*Cv.y + wd*Dv.y;
            v[h*4+2] = wa*A.z + wb*Bv.z + wc*Cv.z + wd*Dv.z;
            v[h*4+3] = wa*A.w + wb*Bv.w + wc*Cv.w + wd*Dv.w;
        }
        float s = 0.0f;
#pragma unroll
        for (int j = 0; j < 8; j++) s += v[j] * v[j];
#pragma unroll
        for (int o = 16; o > 0; o >>= 1) s += __shfl_xor_sync(0xffffffffu, s, o);
        float inv = 1.0f / (sqrtf(s) + 1e-6f);
        float4 w0 = make_float4(v[0]*inv, v[1]*inv, v[2]*inv, v[3]*inv);
        float4 w1 = make_float4(v[4]*inv, v[5]*inv, v[6]*inv, v[7]*inv);
        ((float4*)&feat1s[qi][c0])[0] = w0;
        ((float4*)&feat1s[qi][c0])[1] = w1;
    }
    __syncthreads();

    // ---- Stage B: levels OUTER (keeps one window hot in L1), queries inner ----
#pragma unroll
    for (int l = 0; l < NLEV; l++) {
        const int Hl = NH >> l, Wl = NW >> l;
        const float inv_scl = 1.0f / (float)(1 << l);
#pragma unroll 1
        for (int qi = 0; qi < QPB; qi++) {
            int p = qn_s[qi];
            int b = p >> 12;
            const __half* fb;
            if (l == 0)      fb = h0 + (size_t)b * 64 * 64 * NC;
            else if (l == 1) fb = hA + ((size_t)OFF_L1 + (size_t)b * 32 * 32) * NC;
            else if (l == 2) fb = hA + ((size_t)OFF_L2 + (size_t)b * 16 * 16) * NC;
            else             fb = hA + ((size_t)OFF_L3 + (size_t)b * 8 * 8) * NC;
            float bx = qx_s[qi] * inv_scl;
            float by = qy_s[qi] * inv_scl;
            int ix = (int)floorf(bx);
            int iy = (int)floorf(by);

            float4 t0 = ((const float4*)&feat1s[qi][lane * 8])[0];
            float4 t1 = ((const float4*)&feat1s[qi][lane * 8])[1];
            float q[8] = {t0.x, t0.y, t0.z, t0.w, t1.x, t1.y, t1.z, t1.w};

            int yy = min(max(iy - 3 + wid, 0), Hl - 1);
            const uint4* rowbase = (const uint4*)(fb + (size_t)yy * Wl * NC);
            float acc[8];
#pragma unroll
            for (int wj = 0; wj < 8; wj++) {
                int xx = min(max(ix - 3 + wj, 0), Wl - 1);
                uint4 r = __ldg(&rowbase[xx * (NC / 8) + lane]);
                float2 f0 = __half22float2(*(const __half2*)&r.x);
                float2 f1 = __half22float2(*(const __half2*)&r.y);
                float2 f2 = __half22float2(*(const __half2*)&r.z);
                float2 f3 = __half22float2(*(const __half2*)&r.w);
                acc[wj] = f0.x*q[0] + f0.y*q[1] + f1.x*q[2] + f1.y*q[3] +
                          f2.x*q[4] + f2.y*q[5] + f3.x*q[6] + f3.y*q[7];
            }
            // Multi-value butterfly: 8 sums across 32 lanes in 16 shuffles.
#pragma unroll
            for (int j = 0; j < 4; j++) {
                float u0 = __shfl_xor_sync(0xffffffffu, acc[j], 1);
                float u1 = __shfl_xor_sync(0xffffffffu, acc[j + 4], 1);
                acc[j] = (lane & 1) ? (acc[j + 4] + u1) : (acc[j] + u0);
            }
#pragma unroll
            for (int j = 0; j < 2; j++) {
                float u0 = __shfl_xor_sync(0xffffffffu, acc[j], 2);
                float u1 = __shfl_xor_sync(0xffffffffu, acc[j + 2], 2);
                acc[j] = (lane & 2) ? (acc[j + 2] + u1) : (acc[j] + u0);
            }
            {
                float u0 = __shfl_xor_sync(0xffffffffu, acc[0], 4);
                float u1 = __shfl_xor_sync(0xffffffffu, acc[1], 4);
                acc[0] = (lane & 4) ? (acc[1] + u1) : (acc[0] + u0);
            }
            acc[0] += __shfl_xor_sync(0xffffffffu, acc[0], 8);
            acc[0] += __shfl_xor_sync(0xffffffffu, acc[0], 16);
            int pm = ((lane & 1) << 2) | (lane & 2) | ((lane >> 2) & 1);
            if (lane < 8) Ds[qi][l * 64 + wid * 8 + pm] = acc[0];
        }
    }
    __syncthreads();

    // ---- Blend: 196 threads per query produce all outputs ----
#pragma unroll 1
    for (int qi = 0; qi < QPB; qi++) {
        if (tid < NLEV * NK) {
            int l = tid / NK;
            int k = tid - l * NK;
            int Hl = NH >> l, Wl = NW >> l;
            float bx = qx_s[qi] * (1.0f / (float)(1 << l));
            float by = qy_s[qi] * (1.0f / (float)(1 << l));
            int dy = k / 7 - 3;   // offs is dy-major
            int dx = k % 7 - 3;
            float xk = fminf(fmaxf(bx + (float)dx, 0.0f), (float)(Wl - 1));
            float yk = fminf(fmaxf(by + (float)dy, 0.0f), (float)(Hl - 1));
            float fx = floorf(xk), fy = floorf(yk);
            float xh = fminf(fx + 1.0f, (float)(Wl - 1));
            float yh = fminf(fy + 1.0f, (float)(Hl - 1));
            float wx1 = xk - fx, wx0 = xh - xk;
            float wy1 = yk - fy, wy0 = yh - yk;
            int jx0 = dx + 3, jx1 = dx + 4;
            int jy0 = dy + 3, jy1 = dy + 4;
            float val = wx0 * wy0 * Ds[qi][l * 64 + jy0 * 8 + jx0] +
                        wx0 * wy1 * Ds[qi][l * 64 + jy1 * 8 + jx0] +
                        wx1 * wy0 * Ds[qi][l * 64 + jy0 * 8 + jx1] +
                        wx1 * wy1 * Ds[qi][l * 64 + jy1 * 8 + jx1];
            out[(size_t)qn_s[qi] * (NLEV * NK) + tid] = val;
        }
    }
}

extern "C" void kernel_launch(void* const* d_in, const int* in_sizes, int n_in,
                              void* d_out, int out_size) {
    const float* fmap1   = (const float*)d_in[0];
    const float* fmap2   = (const float*)d_in[1];
    const float* coords1 = (const float*)d_in[2];
    const float* coords2 = (const float*)d_in[3];
    float* out = (float*)d_out;

    float* pyrA;
    __half *h0, *hA;
    cudaGetSymbolAddress((void**)&pyrA, g_pyrA);
    cudaGetSymbolAddress((void**)&h0, g_h0);
    cudaGetSymbolAddress((void**)&hA, g_hA);

    float* pyr1 = pyrA + (size_t)OFF_L1 * NC;
    float* pyr2 = pyrA + (size_t)OFF_L2 * NC;
    float* pyr3 = pyrA + (size_t)OFF_L3 * NC;

    // Spatial counting sort of queries (independent of pyramid).
    sort_kernel<<<1, 1024>>>(coords2);

    // Cascaded pyramid (un-normalized fp32).
    downsample_kernel<<<dim3(32 * 32, NB), 256>>>(fmap2, pyr1, 64, 64);
    downsample_kernel<<<dim3(16 * 16, NB), 256>>>(pyr1, pyr2, 32, 32);
    downsample_kernel<<<dim3(8 * 8, NB), 256>>>(pyr2, pyr3, 16, 16);

    // Normalization -> fp16, both regions in one launch.
    normalize_all_kernel<<<(NB * 64 * 64 + PYR_PX) / 8, 256>>>(fmap2, h0, pyrA, hA);

    // Main correlation kernel: 512 blocks x 16 binned queries.
    corr_kernel<<<NB * NQ / QPB, 256>>>(fmap1, coords1, coords2, h0, hA, out);
}

// round 8
// speedup vs baseline: 1.2870x; 1.2870x over previous
#include <cuda_runtime.h>
#include <cuda_fp16.h>
#include <math.h>

#define NB 2
#define NH 64
#define NW 64
#define NC 256
#define NQ 4096
#define NK 49
#define NLEV 4
#define QPB 8
#define NBINS 256

// Packed pyramid scratch (levels 1..3, un-normalized fp32) and fp16 normalized.
#define PYR_PX (NB * (32*32 + 16*16 + 8*8))
__device__ float  g_pyrA[PYR_PX * NC];
__device__ __half g_h0[NB*64*64*NC];
__device__ __half g_hA[PYR_PX * NC];
__device__ int    g_perm[NB*NQ];   // sorted slot -> packed query index (b*NQ+n)

#define OFF_L1 0
#define OFF_L2 (NB * 32 * 32)
#define OFF_L3 (NB * (32*32 + 16*16))

__device__ __forceinline__ unsigned int h2_as_u32(__half2 h) {
    return *reinterpret_cast<unsigned int*>(&h);
}

// ---------------- Counting sort of queries by level-0 4x4 cell ----------------
__global__ void __launch_bounds__(1024) sort_kernel(const float* __restrict__ coords2) {
    __shared__ int cnt[NB*NBINS];
    __shared__ int sc[NB*NBINS];
    __shared__ int cur[NB*NBINS];
    int tid = threadIdx.x;
    if (tid < NB*NBINS) cnt[tid] = 0;
    __syncthreads();
    int mybin[8];
    int myidx[8];
#pragma unroll
    for (int k = 0; k < 8; k++) {
        int i = tid + k * 1024;          // i = b*NQ + n
        int b = i >> 12;
        float qx = coords2[(size_t)i * 2 + 0];
        float qy = coords2[(size_t)i * 2 + 1];
        int ix = min(max((int)floorf(qx), 0), 63);
        int iy = min(max((int)floorf(qy), 0), 63);
        int bin = b * NBINS + ((iy >> 2) << 4) + (ix >> 2);
        mybin[k] = bin;
        myidx[k] = i;
        atomicAdd(&cnt[bin], 1);
    }
    __syncthreads();
    if (tid < NB*NBINS) sc[tid] = cnt[tid];
    __syncthreads();
    for (int off = 1; off < NB*NBINS; off <<= 1) {
        int v = 0;
        if (tid < NB*NBINS && tid >= off) v = sc[tid - off];
        __syncthreads();
        if (tid < NB*NBINS) sc[tid] += v;
        __syncthreads();
    }
    if (tid < NB*NBINS) cur[tid] = sc[tid] - cnt[tid];   // exclusive
    __syncthreads();
#pragma unroll
    for (int k = 0; k < 8; k++) {
        int slot = atomicAdd(&cur[mybin[k]], 1);
        g_perm[slot] = myidx[k];
    }
}

// jax.image.resize(method='bilinear', antialias=True) 2x downsample taps.
__device__ __forceinline__ void resize_taps(int i, int n, int jj[4], float ww[4]) {
    float c = 2.0f * (float)i + 0.5f;
    float s = 0.0f;
#pragma unroll
    for (int t = 0; t < 4; t++) {
        int j = 2 * i - 1 + t;
        float w = 0.0f;
        if (j >= 0 && j < n) w = 1.0f - 0.5f * fabsf(c - (float)j);
        jj[t] = j < 0 ? 0 : (j > n - 1 ? n - 1 : j);
        ww[t] = w;
        s += w;
    }
    float inv = 1.0f / s;
#pragma unroll
    for (int t = 0; t < 4; t++) ww[t] *= inv;
}

__global__ void downsample_kernel(const float* __restrict__ in, float* __restrict__ out,
                                  int Hi, int Wi) {
    int Ho = Hi >> 1, Wo = Wi >> 1;
    int p = blockIdx.x;
    int b = blockIdx.y;
    int yo = p / Wo, xo = p % Wo;
    int c = threadIdx.x;
    int jy[4], jx[4];
    float wy[4], wx[4];
    resize_taps(yo, Hi, jy, wy);
    resize_taps(xo, Wi, jx, wx);
    const float* ib = in + (size_t)b * Hi * Wi * NC;
    float acc = 0.0f;
#pragma unroll
    for (int a = 0; a < 4; a++) {
        float r = 0.0f;
#pragma unroll
        for (int t = 0; t < 4; t++)
            r += wx[t] * ib[((size_t)jy[a] * Wi + jx[t]) * NC + c];
        acc += wy[a] * r;
    }
    out[(((size_t)b * Ho + yo) * Wo + xo) * NC + c] = acc;
}

// Warp-per-pixel L2 normalize, fp32 in -> fp16 out; handles h0 region then hA region.
__global__ void __launch_bounds__(256) normalize_all_kernel(
    const float* __restrict__ in0, __half* __restrict__ out0,
    const float* __restrict__ inA, __half* __restrict__ outA) {
    int warp = threadIdx.x >> 5, lane = threadIdx.x & 31;
    int p = blockIdx.x * 8 + warp;
    const float* in;
    __half* out;
    if (p < NB * 64 * 64) { in = in0; out = out0; }
    else { in = inA; out = outA; p -= NB * 64 * 64; }
    size_t base = (size_t)p * NC;
    const float4* ip = (const float4*)(in + base);
    float4 a0 = ip[lane * 2];
    float4 a1 = ip[lane * 2 + 1];
    float s = a0.x*a0.x + a0.y*a0.y + a0.z*a0.z + a0.w*a0.w +
              a1.x*a1.x + a1.y*a1.y + a1.z*a1.z + a1.w*a1.w;
#pragma unroll
    for (int o = 16; o > 0; o >>= 1) s += __shfl_xor_sync(0xffffffffu, s, o);
    float inv = 1.0f / (sqrtf(s) + 1e-6f);
    __half2 h0 = __floats2half2_rn(a0.x * inv, a0.y * inv);
    __half2 h1 = __floats2half2_rn(a0.z * inv, a0.w * inv);
    __half2 h2 = __floats2half2_rn(a1.x * inv, a1.y * inv);
    __half2 h3 = __floats2half2_rn(a1.z * inv, a1.w * inv);
    uint4 pk;
    pk.x = h2_as_u32(h0); pk.y = h2_as_u32(h1);
    pk.z = h2_as_u32(h2); pk.w = h2_as_u32(h3);
    ((uint4*)(out + base))[lane] = pk;
}

// Main kernel: one WARP per query, 8 binned queries per 256-thread block.
// No block-level synchronization anywhere; warps fully independent.
__global__ void __launch_bounds__(256) corr_kernel(
    const float* __restrict__ fmap1,
    const float* __restrict__ coords1,
    const float* __restrict__ coords2,
    const __half* __restrict__ h0,
    const __half* __restrict__ hA,
    float* __restrict__ out) {
    int tid = threadIdx.x;
    int lane = tid & 31, wid = tid >> 5;

    __shared__ float Ds[QPB][NLEV * 64];   // 8 KB; warp-private rows

    int p = g_perm[blockIdx.x * QPB + wid];   // broadcast within warp
    int b = p >> 12;

    // ---- Stage A: feat1 in registers (lane owns channels lane*8..lane*8+7) ----
    float cx = __ldg(&coords1[(size_t)p * 2 + 0]);
    float cy = __ldg(&coords1[(size_t)p * 2 + 1]);
    int fx0 = (int)floorf(cx);
    int fy0 = (int)floorf(cy);
    int x0 = min(max(fx0, 0), NW - 1);
    int x1 = min(max(fx0 + 1, 0), NW - 1);
    int y0 = min(max(fy0, 0), NH - 1);
    int y1 = min(max(fy0 + 1, 0), NH - 1);
    float wa = ((float)x1 - cx) * ((float)y1 - cy);
    float wb = ((float)x1 - cx) * (cy - (float)y0);
    float wc = (cx - (float)x0) * ((float)y1 - cy);
    float wd = (cx - (float)x0) * (cy - (float)y0);
    const float* fb1 = fmap1 + (size_t)b * NH * NW * NC;
    int c0 = lane * 8;
    const float4* pa = (const float4*)(fb1 + ((size_t)y0 * NW + x0) * NC + c0);
    const float4* pb = (const float4*)(fb1 + ((size_t)y1 * NW + x0) * NC + c0);
    const float4* pc = (const float4*)(fb1 + ((size_t)y0 * NW + x1) * NC + c0);
    const float4* pd = (const float4*)(fb1 + ((size_t)y1 * NW + x1) * NC + c0);
    float v[8];
#pragma unroll
    for (int h = 0; h < 2; h++) {
        float4 A = __ldcg(pa + h), Bv = __ldcg(pb + h), Cv = __ldcg(pc + h), Dv = __ldcg(pd + h);
        v[h*4+0] = wa*A.x + wb*Bv.x + wc*Cv.x + wd*Dv.x;
        v[h*4+1] = wa*A.y + wb*Bv.y + wc*Cv.y + wd*Dv.y;
        v[h*4+2] = wa*A.z + wb*Bv.z + wc*Cv.z + wd*Dv.z;
        v[h*4+3] = wa*A.w + wb*Bv.w + wc*Cv.w + wd*Dv.w;
    }
    float s = 0.0f;
#pragma unroll
    for (int j = 0; j < 8; j++) s += v[j] * v[j];
#pragma unroll
    for (int o = 16; o > 0; o >>= 1) s += __shfl_xor_sync(0xffffffffu, s, o);
    float inv = 1.0f / (sqrtf(s) + 1e-6f);
    // Query slice as half2 (4 regs) for HFMA2 inner loop.
    __half2 qh[4];
#pragma unroll
    for (int j = 0; j < 4; j++)
        qh[j] = __floats2half2_rn(v[2*j] * inv, v[2*j+1] * inv);

    float qx = __ldg(&coords2[(size_t)p * 2 + 0]);
    float qy = __ldg(&coords2[(size_t)p * 2 + 1]);

    // ---- Stage B: 4 levels x 64 window dots, all warp-local ----
#pragma unroll
    for (int l = 0; l < NLEV; l++) {
        const int Hl = NH >> l, Wl = NW >> l;
        const __half* fb;
        if (l == 0)      fb = h0 + (size_t)b * 64 * 64 * NC;
        else if (l == 1) fb = hA + ((size_t)OFF_L1 + (size_t)b * 32 * 32) * NC;
        else if (l == 2) fb = hA + ((size_t)OFF_L2 + (size_t)b * 16 * 16) * NC;
        else             fb = hA + ((size_t)OFF_L3 + (size_t)b * 8 * 8) * NC;
        float bx = qx * (1.0f / (float)(1 << l));
        float by = qy * (1.0f / (float)(1 << l));
        int ix = (int)floorf(bx);
        int iy = (int)floorf(by);

#pragma unroll
        for (int chunk = 0; chunk < 8; chunk++) {     // window row
            int yy = min(max(iy - 3 + chunk, 0), Hl - 1);
            const uint4* rowbase = (const uint4*)(fb + (size_t)yy * Wl * NC);
            float acc[8];
#pragma unroll
            for (int wj = 0; wj < 8; wj++) {          // window col
                int xx = min(max(ix - 3 + wj, 0), Wl - 1);
                uint4 r = __ldg(&rowbase[xx * (NC / 8) + lane]);
                // half2 dot over this lane's 8 channels, float finalize.
                __half2 ah = __hmul2(*(const __half2*)&r.x, qh[0]);
                ah = __hfma2(*(const __half2*)&r.y, qh[1], ah);
                ah = __hfma2(*(const __half2*)&r.z, qh[2], ah);
                ah = __hfma2(*(const __half2*)&r.w, qh[3], ah);
                float2 f = __half22float2(ah);
                acc[wj] = f.x + f.y;
            }
            // Multi-value butterfly: 8 sums across 32 lanes in 16 shuffles.
#pragma unroll
            for (int j = 0; j < 4; j++) {
                float u0 = __shfl_xor_sync(0xffffffffu, acc[j], 1);
                float u1 = __shfl_xor_sync(0xffffffffu, acc[j + 4], 1);
                acc[j] = (lane & 1) ? (acc[j + 4] + u1) : (acc[j] + u0);
            }
#pragma unroll
            for (int j = 0; j < 2; j++) {
                float u0 = __shfl_xor_sync(0xffffffffu, acc[j], 2);
                float u1 = __shfl_xor_sync(0xffffffffu, acc[j + 2], 2);
                acc[j] = (lane & 2) ? (acc[j + 2] + u1) : (acc[j] + u0);
            }
            {
                float u0 = __shfl_xor_sync(0xffffffffu, acc[0], 4);
                float u1 = __shfl_xor_sync(0xffffffffu, acc[1], 4);
                acc[0] = (lane & 4) ? (acc[1] + u1) : (acc[0] + u0);
            }
            acc[0] += __shfl_xor_sync(0xffffffffu, acc[0], 8);
            acc[0] += __shfl_xor_sync(0xffffffffu, acc[0], 16);
            int pm = ((lane & 1) << 2) | (lane & 2) | ((lane >> 2) & 1);
            if (lane < 8) Ds[wid][l * 64 + chunk * 8 + pm] = acc[0];
        }
    }
    __syncwarp();

    // ---- Blend: warp produces its query's 196 outputs (lane-strided) ----
    for (int t = lane; t < NLEV * NK; t += 32) {
        int l = t / NK;
        int k = t - l * NK;
        int Hl = NH >> l, Wl = NW >> l;
        float bx = qx * (1.0f / (float)(1 << l));
        float by = qy * (1.0f / (float)(1 << l));
        int dy = k / 7 - 3;   // offs is dy-major
        int dx = k % 7 - 3;
        float xk = fminf(fmaxf(bx + (float)dx, 0.0f), (float)(Wl - 1));
        float yk = fminf(fmaxf(by + (float)dy, 0.0f), (float)(Hl - 1));
        float fx = floorf(xk), fy = floorf(yk);
        float xh = fminf(fx + 1.0f, (float)(Wl - 1));
        float yh = fminf(fy + 1.0f, (float)(Hl - 1));
        float wx1 = xk - fx, wx0 = xh - xk;
        float wy1 = yk - fy, wy0 = yh - yk;
        int jx0 = dx + 3, jx1 = dx + 4;
        int jy0 = dy + 3, jy1 = dy + 4;
        float val = wx0 * wy0 * Ds[wid][l * 64 + jy0 * 8 + jx0] +
                    wx0 * wy1 * Ds[wid][l * 64 + jy1 * 8 + jx0] +
                    wx1 * wy0 * Ds[wid][l * 64 + jy0 * 8 + jx1] +
                    wx1 * wy1 * Ds[wid][l * 64 + jy1 * 8 + jx1];
        out[(size_t)p * (NLEV * NK) + t] = val;
    }
}

extern "C" void kernel_launch(void* const* d_in, const int* in_sizes, int n_in,
                              void* d_out, int out_size) {
    const float* fmap1   = (const float*)d_in[0];
    const float* fmap2   = (const float*)d_in[1];
    const float* coords1 = (const float*)d_in[2];
    const float* coords2 = (const float*)d_in[3];
    float* out = (float*)d_out;

    float* pyrA;
    __half *h0, *hA;
    cudaGetSymbolAddress((void**)&pyrA, g_pyrA);
    cudaGetSymbolAddress((void**)&h0, g_h0);
    cudaGetSymbolAddress((void**)&hA, g_hA);

    float* pyr1 = pyrA + (size_t)OFF_L1 * NC;
    float* pyr2 = pyrA + (size_t)OFF_L2 * NC;
    float* pyr3 = pyrA + (size_t)OFF_L3 * NC;

    // Spatial counting sort of queries (independent of pyramid).
    sort_kernel<<<1, 1024>>>(coords2);

    // Cascaded pyramid (un-normalized fp32).
    downsample_kernel<<<dim3(32 * 32, NB), 256>>>(fmap2, pyr1, 64, 64);
    downsample_kernel<<<dim3(16 * 16, NB), 256>>>(pyr1, pyr2, 32, 32);
    downsample_kernel<<<dim3(8 * 8, NB), 256>>>(pyr2, pyr3, 16, 16);

    // Normalization -> fp16, both regions in one launch.
    normalize_all_kernel<<<(NB * 64 * 64 + PYR_PX) / 8, 256>>>(fmap2, h0, pyrA, hA);

    // Main correlation kernel: 2048 blocks x 8 binned queries (warp each).
    corr_kernel<<<NB * NQ / QPB, 256>>>(fmap1, coords1, coords2, h0, hA, out);
}

// round 12
// speedup vs baseline: 1.3148x; 1.0216x over previous
#include <cuda_runtime.h>
#include <cuda_fp16.h>
#include <math.h>
#include <stdint.h>

typedef unsigned int       u32;
typedef unsigned long long u64;

#define NB 2
#define NH 64
#define NW 64
#define NC 256
#define NQ 4096
#define NK 49
#define NLEV 4
#define NBINS 256

#define PYR_PX (NB * (32*32 + 16*16 + 8*8))
__device__ float  g_pyrA[PYR_PX * NC];
__device__ __half g_h0[NB*64*64*NC];
__device__ __half g_hA[PYR_PX * NC];
__device__ int    g_perm[NB*NQ];       // sorted slot -> packed query index
__device__ int    g_binoff[NB*NBINS + 1];
__device__ __half g_feat1h[NB*NQ*NC];  // normalized feat1, SORTED-SLOT order

#define OFF_L1 0
#define OFF_L2 (NB * 32 * 32)
#define OFF_L3 (NB * (32*32 + 16*16))

// ---------------- helpers ----------------
__device__ __forceinline__ u32 h2_as_u32(__half2 h) {
    return *reinterpret_cast<u32*>(&h);
}
__device__ __forceinline__ u32 smem_u32(const void* p) {
    u32 a;
    asm("{ .reg .u64 t; cvta.to.shared.u64 t, %1; cvt.u32.u64 %0, t; }" : "=r"(a) : "l"(p));
    return a;
}
__device__ __forceinline__ void ldsm_x4(u32& r0, u32& r1, u32& r2, u32& r3, u32 a) {
    asm volatile("ldmatrix.sync.aligned.m8n8.x4.shared.b16 {%0,%1,%2,%3}, [%4];"
                 : "=r"(r0), "=r"(r1), "=r"(r2), "=r"(r3) : "r"(a));
}
__device__ __forceinline__ void ldsm_x2(u32& r0, u32& r1, u32 a) {
    asm volatile("ldmatrix.sync.aligned.m8n8.x2.shared.b16 {%0,%1}, [%2];"
                 : "=r"(r0), "=r"(r1) : "r"(a));
}
__device__ __forceinline__ void mma16816(float* c, u32 a0, u32 a1, u32 a2, u32 a3,
                                         u32 b0, u32 b1) {
    asm volatile("mma.sync.aligned.m16n8k16.row.col.f32.f16.f16.f32 "
                 "{%0,%1,%2,%3}, {%4,%5,%6,%7}, {%8,%9}, {%0,%1,%2,%3};"
                 : "+f"(c[0]), "+f"(c[1]), "+f"(c[2]), "+f"(c[3])
                 : "r"(a0), "r"(a1), "r"(a2), "r"(a3), "r"(b0), "r"(b1));
}

// ---------------- Counting sort of queries by level-0 4x4 cell ----------------
__global__ void __launch_bounds__(1024) sort_kernel(const float* __restrict__ coords2) {
    __shared__ int cnt[NB*NBINS];
    __shared__ int sc[NB*NBINS];
    __shared__ int cur[NB*NBINS];
    int tid = threadIdx.x;
    if (tid < NB*NBINS) cnt[tid] = 0;
    __syncthreads();
    int mybin[8], myidx[8];
#pragma unroll
    for (int k = 0; k < 8; k++) {
        int i = tid + k * 1024;
        int b = i >> 12;
        float qx = coords2[(size_t)i * 2 + 0];
        float qy = coords2[(size_t)i * 2 + 1];
        int ix = min(max((int)floorf(qx), 0), 63);
        int iy = min(max((int)floorf(qy), 0), 63);
        int bin = b * NBINS + ((iy >> 2) << 4) + (ix >> 2);
        mybin[k] = bin; myidx[k] = i;
        atomicAdd(&cnt[bin], 1);
    }
    __syncthreads();
    if (tid < NB*NBINS) sc[tid] = cnt[tid];
    __syncthreads();
    for (int off = 1; off < NB*NBINS; off <<= 1) {
        int v = 0;
        if (tid < NB*NBINS && tid >= off) v = sc[tid - off];
        __syncthreads();
        if (tid < NB*NBINS) sc[tid] += v;
        __syncthreads();
    }
    if (tid < NB*NBINS) {
        cur[tid] = sc[tid] - cnt[tid];
        g_binoff[tid] = sc[tid] - cnt[tid];
    }
    if (tid == 0) g_binoff[NB*NBINS] = NB*NQ;
    __syncthreads();
#pragma unroll
    for (int k = 0; k < 8; k++) {
        int slot = atomicAdd(&cur[mybin[k]], 1);
        g_perm[slot] = myidx[k];
    }
}

// ---------------- feat1: normalize(bilinear(fmap1, coords1)) -> fp16, sorted order ----
__global__ void __launch_bounds__(256) feat1_kernel(
    const float* __restrict__ fmap1, const float* __restrict__ coords1) {
    int lane = threadIdx.x & 31, wid = threadIdx.x >> 5;
    int s = blockIdx.x * 8 + wid;         // sorted slot
    int p = g_perm[s];
    int b = p >> 12;
    float cx = __ldg(&coords1[(size_t)p * 2 + 0]);
    float cy = __ldg(&coords1[(size_t)p * 2 + 1]);
    int fx0 = (int)floorf(cx), fy0 = (int)floorf(cy);
    int x0 = min(max(fx0, 0), NW - 1), x1 = min(max(fx0 + 1, 0), NW - 1);
    int y0 = min(max(fy0, 0), NH - 1), y1 = min(max(fy0 + 1, 0), NH - 1);
    float wa = ((float)x1 - cx) * ((float)y1 - cy);
    float wb = ((float)x1 - cx) * (cy - (float)y0);
    float wc = (cx - (float)x0) * ((float)y1 - cy);
    float wd = (cx - (float)x0) * (cy - (float)y0);
    const float* fb1 = fmap1 + (size_t)b * NH * NW * NC;
    int c0 = lane * 8;
    const float4* pa = (const float4*)(fb1 + ((size_t)y0 * NW + x0) * NC + c0);
    const float4* pb = (const float4*)(fb1 + ((size_t)y1 * NW + x0) * NC + c0);
    const float4* pc = (const float4*)(fb1 + ((size_t)y0 * NW + x1) * NC + c0);
    const float4* pd = (const float4*)(fb1 + ((size_t)y1 * NW + x1) * NC + c0);
    float v[8];
#pragma unroll
    for (int h = 0; h < 2; h++) {
        float4 A = __ldcg(pa + h), Bv = __ldcg(pb + h), Cv = __ldcg(pc + h), Dv = __ldcg(pd + h);
        v[h*4+0] = wa*A.x + wb*Bv.x + wc*Cv.x + wd*Dv.x;
        v[h*4+1] = wa*A.y + wb*Bv.y + wc*Cv.y + wd*Dv.y;
        v[h*4+2] = wa*A.z + wb*Bv.z + wc*Cv.z + wd*Dv.z;
        v[h*4+3] = wa*A.w + wb*Bv.w + wc*Cv.w + wd*Dv.w;
    }
    float s2 = 0.0f;
#pragma unroll
    for (int j = 0; j < 8; j++) s2 += v[j] * v[j];
#pragma unroll
    for (int o = 16; o > 0; o >>= 1) s2 += __shfl_xor_sync(0xffffffffu, s2, o);
    float inv = 1.0f / (sqrtf(s2) + 1e-6f);
    uint4 pk;
    pk.x = h2_as_u32(__floats2half2_rn(v[0]*inv, v[1]*inv));
    pk.y = h2_as_u32(__floats2half2_rn(v[2]*inv, v[3]*inv));
    pk.z = h2_as_u32(__floats2half2_rn(v[4]*inv, v[5]*inv));
    pk.w = h2_as_u32(__floats2half2_rn(v[6]*inv, v[7]*inv));
    ((uint4*)(g_feat1h + (size_t)s * NC))[lane] = pk;
}

// ---------------- pyramid + normalize ----------------
__device__ __forceinline__ void resize_taps(int i, int n, int jj[4], float ww[4]) {
    float c = 2.0f * (float)i + 0.5f;
    float s = 0.0f;
#pragma unroll
    for (int t = 0; t < 4; t++) {
        int j = 2 * i - 1 + t;
        float w = 0.0f;
        if (j >= 0 && j < n) w = 1.0f - 0.5f * fabsf(c - (float)j);
        jj[t] = j < 0 ? 0 : (j > n - 1 ? n - 1 : j);
        ww[t] = w;
        s += w;
    }
    float inv = 1.0f / s;
#pragma unroll
    for (int t = 0; t < 4; t++) ww[t] *= inv;
}

__global__ void downsample_kernel(const float* __restrict__ in, float* __restrict__ out,
                                  int Hi, int Wi) {
    int Ho = Hi >> 1, Wo = Wi >> 1;
    int p = blockIdx.x, b = blockIdx.y;
    int yo = p / Wo, xo = p % Wo;
    int c = threadIdx.x;
    int jy[4], jx[4];
    float wy[4], wx[4];
    resize_taps(yo, Hi, jy, wy);
    resize_taps(xo, Wi, jx, wx);
    const float* ib = in + (size_t)b * Hi * Wi * NC;
    float acc = 0.0f;
#pragma unroll
    for (int a = 0; a < 4; a++) {
        float r = 0.0f;
#pragma unroll
        for (int t = 0; t < 4; t++)
            r += wx[t] * ib[((size_t)jy[a] * Wi + jx[t]) * NC + c];
        acc += wy[a] * r;
    }
    out[(((size_t)b * Ho + yo) * Wo + xo) * NC + c] = acc;
}

__global__ void __launch_bounds__(256) normalize_all_kernel(
    const float* __restrict__ in0, __half* __restrict__ out0,
    const float* __restrict__ inA, __half* __restrict__ outA) {
    int warp = threadIdx.x >> 5, lane = threadIdx.x & 31;
    int p = blockIdx.x * 8 + warp;
    const float* in;
    __half* out;
    if (p < NB * 64 * 64) { in = in0; out = out0; }
    else { in = inA; out = outA; p -= NB * 64 * 64; }
    size_t base = (size_t)p * NC;
    const float4* ip = (const float4*)(in + base);
    float4 a0 = ip[lane * 2];
    float4 a1 = ip[lane * 2 + 1];
    float s = a0.x*a0.x + a0.y*a0.y + a0.z*a0.z + a0.w*a0.w +
              a1.x*a1.x + a1.y*a1.y + a1.z*a1.z + a1.w*a1.w;
#pragma unroll
    for (int o = 16; o > 0; o >>= 1) s += __shfl_xor_sync(0xffffffffu, s, o);
    float inv = 1.0f / (sqrtf(s) + 1e-6f);
    uint4 pk;
    pk.x = h2_as_u32(__floats2half2_rn(a0.x*inv, a0.y*inv));
    pk.y = h2_as_u32(__floats2half2_rn(a0.z*inv, a0.w*inv));
    pk.z = h2_as_u32(__floats2half2_rn(a1.x*inv, a1.y*inv));
    pk.w = h2_as_u32(__floats2half2_rn(a1.z*inv, a1.w*inv));
    ((uint4*)(out + base))[lane] = pk;
}

// ---------------- Main: one block per cell, mma.sync GEMM per (level, group) ----
// Padded smem layout (16B aligned). A/B row stride 528B (= 33x16B, conflict-free).
#define SA_B   528                       // bytes per row
#define SM_A   0                         // 128 * 528 = 67584
#define SM_B   67584                     // 16 * 528 = 8448
#define SM_D   76032                     // 128 * 17 * 4 = 8704
#define SM_QPS 84736
#define SM_QX  84800
#define SM_QY  84864
#define SMEM_DYN 84992

__global__ void __launch_bounds__(256) corr_kernel(
    const float* __restrict__ coords2,
    const __half* __restrict__ h0,
    const __half* __restrict__ hA,
    float* __restrict__ out) {
    extern __shared__ __align__(16) char sal[];
    u32 sb = smem_u32(sal);

    int tid = threadIdx.x, lane = tid & 31, wid = tid >> 5;
    int bid = blockIdx.x;              // 0..511
    int b = bid >> 8;
    int cell = bid & 255;
    int cx = cell & 15, cy = cell >> 4;
    int start = g_binoff[bid], end = g_binoff[bid + 1];
    int nq = end - start;

    float* Dsm = (float*)(sal + SM_D);
    int*   qps = (int*)(sal + SM_QPS);
    float* qxs = (float*)(sal + SM_QX);
    float* qys = (float*)(sal + SM_QY);

    if (nq > 0) {
#pragma unroll 1
        for (int l = 0; l < NLEV; l++) {
            const int Wl = NW >> l, Hl = NH >> l;
            const float inv_scl = 1.0f / (float)(1 << l);
            const __half* fb;
            if (l == 0)      fb = h0 + (size_t)b * 64 * 64 * NC;
            else if (l == 1) fb = hA + ((size_t)OFF_L1 + (size_t)b * 32 * 32) * NC;
            else if (l == 2) fb = hA + ((size_t)OFF_L2 + (size_t)b * 16 * 16) * NC;
            else             fb = hA + ((size_t)OFF_L3 + (size_t)b * 8 * 8) * NC;
            // cell-static integer window union at this level
            int ixlo = (l == 0) ? cx*4 : (l == 1) ? cx*2 : (l == 2) ? cx : (cx >> 1);
            int iylo = (l == 0) ? cy*4 : (l == 1) ? cy*2 : (l == 2) ? cy : (cy >> 1);
            int span = (l == 0) ? 3 : (l == 1) ? 1 : 0;
            int ux0 = max(0, ixlo - 3), ux1 = min(Wl - 1, ixlo + span + 4);
            int uy0 = max(0, iylo - 3), uy1 = min(Hl - 1, iylo + span + 4);
            int uw = ux1 - ux0 + 1;
            int upix = uw * (uy1 - uy0 + 1);   // <= 121

            // ---- stage union window rows into padded A smem ----
            for (int r = wid; r < upix; r += 8) {
                int ry = r / uw, rx = r - ry * uw;
                int yy = uy0 + ry, xx = ux0 + rx;
                uint4 v = __ldg((const uint4*)(fb + ((size_t)yy * Wl + xx) * NC) + lane);
                *(uint4*)(sal + SM_A + r * SA_B + lane * 16) = v;
            }
            __syncthreads();

            int ngroups = (nq + 15) >> 4;
#pragma unroll 1
            for (int g = 0; g < ngroups; g++) {
                int gs = start + g * 16;
                int vcnt = min(16, end - gs);
                // ---- stage B: up to 16 feat1 rows, padded stride ----
                for (int qi = wid; qi < 16; qi += 8) {
                    if (qi < vcnt) {
                        uint4 v = __ldg((const uint4*)(g_feat1h + (size_t)(gs + qi) * NC) + lane);
                        *(uint4*)(sal + SM_B + qi * SA_B + lane * 16) = v;
                    }
                }
                if (tid < 16 && tid < vcnt) {
                    int p = g_perm[gs + tid];
                    qps[tid] = p;
                    qxs[tid] = __ldg(&coords2[(size_t)p * 2 + 0]);
                    qys[tid] = __ldg(&coords2[(size_t)p * 2 + 1]);
                }
                __syncthreads();

                // ---- MMA: warp `wid` computes D rows [16*wid, 16*wid+16) x 16 queries ----
                {
                    float c0[4] = {0.f, 0.f, 0.f, 0.f};
                    float c1[4] = {0.f, 0.f, 0.f, 0.f};
                    u32 a_base = sb + SM_A + (16 * wid + (lane & 15)) * SA_B + (lane >> 4) * 16;
                    u32 b_base = sb + SM_B + (lane & 7) * SA_B + ((lane >> 3) & 1) * 16;
#pragma unroll
                    for (int kc = 0; kc < 16; kc++) {
                        u32 a0, a1, a2, a3, b0, b1, b2, b3;
                        ldsm_x4(a0, a1, a2, a3, a_base + kc * 32);
                        ldsm_x2(b0, b1, b_base + kc * 32);
                        mma16816(c0, a0, a1, a2, a3, b0, b1);
                        ldsm_x2(b2, b3, b_base + 8 * SA_B + kc * 32);
                        mma16816(c1, a0, a1, a2, a3, b2, b3);
                    }
                    int row0 = 16 * wid + (lane >> 2);
                    int col = 2 * (lane & 3);
                    Dsm[row0 * 17 + col]           = c0[0];
                    Dsm[row0 * 17 + col + 1]       = c0[1];
                    Dsm[(row0 + 8) * 17 + col]     = c0[2];
                    Dsm[(row0 + 8) * 17 + col + 1] = c0[3];
                    Dsm[row0 * 17 + 8 + col]           = c1[0];
                    Dsm[row0 * 17 + 8 + col + 1]       = c1[1];
                    Dsm[(row0 + 8) * 17 + 8 + col]     = c1[2];
                    Dsm[(row0 + 8) * 17 + 8 + col + 1] = c1[3];
                }
                __syncthreads();

                // ---- blend: thread t -> query t/16, outputs k = t%16 (+16,+32) ----
                int qi = tid >> 4, j = tid & 15;
                if (qi < vcnt) {
                    float bx = qxs[qi] * inv_scl;
                    float by = qys[qi] * inv_scl;
                    int p = qps[qi];
                    for (int k = j; k < NK; k += 16) {
                        int dy = k / 7 - 3, dx = k % 7 - 3;
                        float xk = fminf(fmaxf(bx + (float)dx, 0.0f), (float)(Wl - 1));
                        float yk = fminf(fmaxf(by + (float)dy, 0.0f), (float)(Hl - 1));
                        float fx = floorf(xk), fy = floorf(yk);
                        float xh = fminf(fx + 1.0f, (float)(Wl - 1));
                        float yh = fminf(fy + 1.0f, (float)(Hl - 1));
                        float wx1 = xk - fx, wx0 = xh - xk;
                        float wy1 = yk - fy, wy0 = yh - yk;
                        int px0 = (int)fx - ux0, px1 = (int)xh - ux0;
                        int py0 = (int)fy - uy0, py1 = (int)yh - uy0;
                        float val = wx0 * wy0 * Dsm[(py0 * uw + px0) * 17 + qi] +
                                    wx0 * wy1 * Dsm[(py1 * uw + px0) * 17 + qi] +
                                    wx1 * wy0 * Dsm[(py0 * uw + px1) * 17 + qi] +
                                    wx1 * wy1 * Dsm[(py1 * uw + px1) * 17 + qi];
                        out[(size_t)p * (NLEV * NK) + l * NK + k] = val;
                    }
                }
                __syncthreads();   // before next group's B staging / window overwrite
            }
        }
    }
}

extern "C" void kernel_launch(void* const* d_in, const int* in_sizes, int n_in,
                              void* d_out, int out_size) {
    const float* fmap1   = (const float*)d_in[0];
    const float* fmap2   = (const float*)d_in[1];
    const float* coords1 = (const float*)d_in[2];
    const float* coords2 = (const float*)d_in[3];
    float* out = (float*)d_out;

    float* pyrA;
    __half *h0, *hA;
    cudaGetSymbolAddress((void**)&pyrA, g_pyrA);
    cudaGetSymbolAddress((void**)&h0, g_h0);
    cudaGetSymbolAddress((void**)&hA, g_hA);

    float* pyr1 = pyrA + (size_t)OFF_L1 * NC;
    float* pyr2 = pyrA + (size_t)OFF_L2 * NC;
    float* pyr3 = pyrA + (size_t)OFF_L3 * NC;

    cudaFuncSetAttribute(corr_kernel, cudaFuncAttributeMaxDynamicSharedMemorySize, SMEM_DYN);

    sort_kernel<<<1, 1024>>>(coords2);
    feat1_kernel<<<NB * NQ / 8, 256>>>(fmap1, coords1);

    downsample_kernel<<<dim3(32 * 32, NB), 256>>>(fmap2, pyr1, 64, 64);
    downsample_kernel<<<dim3(16 * 16, NB), 256>>>(pyr1, pyr2, 32, 32);
    downsample_kernel<<<dim3(8 * 8, NB), 256>>>(pyr2, pyr3, 16, 16);
    normalize_all_kernel<<<(NB * 64 * 64 + PYR_PX) / 8, 256>>>(fmap2, h0, pyrA, hA);

    corr_kernel<<<NB * NBINS, 256, SMEM_DYN>>>(coords2, h0, hA, out);
}

// round 13
// speedup vs baseline: 1.4484x; 1.1016x over previous
#include <cuda_runtime.h>
#include <cuda_fp16.h>
#include <math.h>
#include <stdint.h>

typedef unsigned int       u32;
typedef unsigned long long u64;

#define NB 2
#define NH 64
#define NW 64
#define NC 256
#define NQ 4096
#define NK 49
#define NLEV 4
#define NBINS 256

#define PYR_PX (NB * (32*32 + 16*16 + 8*8))
__device__ float  g_pyrA[PYR_PX * NC];
__device__ __half g_h0[NB*64*64*NC];
__device__ __half g_hA[PYR_PX * NC];
__device__ int    g_perm[NB*NQ];       // sorted slot -> packed query index
__device__ int    g_binoff[NB*NBINS + 1];
__device__ __half g_feat1h[NB*NQ*NC];  // normalized feat1, NATURAL (p) order

#define OFF_L1 0
#define OFF_L2 (NB * 32 * 32)
#define OFF_L3 (NB * (32*32 + 16*16))

// ---------------- helpers ----------------
__device__ __forceinline__ u32 h2_as_u32(__half2 h) {
    return *reinterpret_cast<u32*>(&h);
}
__device__ __forceinline__ u32 smem_u32(const void* p) {
    u32 a;
    asm("{ .reg .u64 t; cvta.to.shared.u64 t, %1; cvt.u32.u64 %0, t; }" : "=r"(a) : "l"(p));
    return a;
}
__device__ __forceinline__ void ldsm_x4(u32& r0, u32& r1, u32& r2, u32& r3, u32 a) {
    asm volatile("ldmatrix.sync.aligned.m8n8.x4.shared.b16 {%0,%1,%2,%3}, [%4];"
                 : "=r"(r0), "=r"(r1), "=r"(r2), "=r"(r3) : "r"(a));
}
__device__ __forceinline__ void ldsm_x2(u32& r0, u32& r1, u32 a) {
    asm volatile("ldmatrix.sync.aligned.m8n8.x2.shared.b16 {%0,%1}, [%2];"
                 : "=r"(r0), "=r"(r1) : "r"(a));
}
__device__ __forceinline__ void mma16816(float* c, u32 a0, u32 a1, u32 a2, u32 a3,
                                         u32 b0, u32 b1) {
    asm volatile("mma.sync.aligned.m16n8k16.row.col.f32.f16.f16.f32 "
                 "{%0,%1,%2,%3}, {%4,%5,%6,%7}, {%8,%9}, {%0,%1,%2,%3};"
                 : "+f"(c[0]), "+f"(c[1]), "+f"(c[2]), "+f"(c[3])
                 : "r"(a0), "r"(a1), "r"(a2), "r"(a3), "r"(b0), "r"(b1));
}

// ---------------- Counting sort of queries by level-0 4x4 cell ----------------
__global__ void __launch_bounds__(1024) sort_kernel(const float* __restrict__ coords2) {
    __shared__ int cnt[NB*NBINS];
    __shared__ int sc[NB*NBINS];
    __shared__ int cur[NB*NBINS];
    int tid = threadIdx.x;
    if (tid < NB*NBINS) cnt[tid] = 0;
    __syncthreads();
    int mybin[8], myidx[8];
#pragma unroll
    for (int k = 0; k < 8; k++) {
        int i = tid + k * 1024;
        int b = i >> 12;
        float qx = coords2[(size_t)i * 2 + 0];
        float qy = coords2[(size_t)i * 2 + 1];
        int ix = min(max((int)floorf(qx), 0), 63);
        int iy = min(max((int)floorf(qy), 0), 63);
        int bin = b * NBINS + ((iy >> 2) << 4) + (ix >> 2);
        mybin[k] = bin; myidx[k] = i;
        atomicAdd(&cnt[bin], 1);
    }
    __syncthreads();
    if (tid < NB*NBINS) sc[tid] = cnt[tid];
    __syncthreads();
    for (int off = 1; off < NB*NBINS; off <<= 1) {
        int v = 0;
        if (tid < NB*NBINS && tid >= off) v = sc[tid - off];
        __syncthreads();
        if (tid < NB*NBINS) sc[tid] += v;
        __syncthreads();
    }
    if (tid < NB*NBINS) {
        cur[tid] = sc[tid] - cnt[tid];
        g_binoff[tid] = sc[tid] - cnt[tid];
    }
    if (tid == 0) g_binoff[NB*NBINS] = NB*NQ;
    __syncthreads();
#pragma unroll
    for (int k = 0; k < 8; k++) {
        int slot = atomicAdd(&cur[mybin[k]], 1);
        g_perm[slot] = myidx[k];
    }
}

// ---------------- fused: feat1 (natural order) + normalize level-0 ----------------
__global__ void __launch_bounds__(256) feat1_norm0_kernel(
    const float* __restrict__ fmap1, const float* __restrict__ coords1,
    const float* __restrict__ fmap2, __half* __restrict__ h0) {
    int lane = threadIdx.x & 31, wid = threadIdx.x >> 5;
    if (blockIdx.x < NB * NQ / 8) {
        // ---- feat1: warp per query, natural index p ----
        int p = blockIdx.x * 8 + wid;
        int b = p >> 12;
        float cx = __ldg(&coords1[(size_t)p * 2 + 0]);
        float cy = __ldg(&coords1[(size_t)p * 2 + 1]);
        int fx0 = (int)floorf(cx), fy0 = (int)floorf(cy);
        int x0 = min(max(fx0, 0), NW - 1), x1 = min(max(fx0 + 1, 0), NW - 1);
        int y0 = min(max(fy0, 0), NH - 1), y1 = min(max(fy0 + 1, 0), NH - 1);
        float wa = ((float)x1 - cx) * ((float)y1 - cy);
        float wb = ((float)x1 - cx) * (cy - (float)y0);
        float wc = (cx - (float)x0) * ((float)y1 - cy);
        float wd = (cx - (float)x0) * (cy - (float)y0);
        const float* fb1 = fmap1 + (size_t)b * NH * NW * NC;
        int c0 = lane * 8;
        const float4* pa = (const float4*)(fb1 + ((size_t)y0 * NW + x0) * NC + c0);
        const float4* pb = (const float4*)(fb1 + ((size_t)y1 * NW + x0) * NC + c0);
        const float4* pc = (const float4*)(fb1 + ((size_t)y0 * NW + x1) * NC + c0);
        const float4* pd = (const float4*)(fb1 + ((size_t)y1 * NW + x1) * NC + c0);
        float v[8];
#pragma unroll
        for (int h = 0; h < 2; h++) {
            float4 A = __ldcg(pa + h), Bv = __ldcg(pb + h), Cv = __ldcg(pc + h), Dv = __ldcg(pd + h);
            v[h*4+0] = wa*A.x + wb*Bv.x + wc*Cv.x + wd*Dv.x;
            v[h*4+1] = wa*A.y + wb*Bv.y + wc*Cv.y + wd*Dv.y;
            v[h*4+2] = wa*A.z + wb*Bv.z + wc*Cv.z + wd*Dv.z;
            v[h*4+3] = wa*A.w + wb*Bv.w + wc*Cv.w + wd*Dv.w;
        }
        float s2 = 0.0f;
#pragma unroll
        for (int j = 0; j < 8; j++) s2 += v[j] * v[j];
#pragma unroll
        for (int o = 16; o > 0; o >>= 1) s2 += __shfl_xor_sync(0xffffffffu, s2, o);
        float inv = 1.0f / (sqrtf(s2) + 1e-6f);
        uint4 pk;
        pk.x = h2_as_u32(__floats2half2_rn(v[0]*inv, v[1]*inv));
        pk.y = h2_as_u32(__floats2half2_rn(v[2]*inv, v[3]*inv));
        pk.z = h2_as_u32(__floats2half2_rn(v[4]*inv, v[5]*inv));
        pk.w = h2_as_u32(__floats2half2_rn(v[6]*inv, v[7]*inv));
        ((uint4*)(g_feat1h + (size_t)p * NC))[lane] = pk;
    } else {
        // ---- normalize level 0: warp per pixel ----
        int p = (blockIdx.x - NB * NQ / 8) * 8 + wid;   // 0..8191
        size_t base = (size_t)p * NC;
        const float4* ip = (const float4*)(fmap2 + base);
        float4 a0 = ip[lane * 2];
        float4 a1 = ip[lane * 2 + 1];
        float s = a0.x*a0.x + a0.y*a0.y + a0.z*a0.z + a0.w*a0.w +
                  a1.x*a1.x + a1.y*a1.y + a1.z*a1.z + a1.w*a1.w;
#pragma unroll
        for (int o = 16; o > 0; o >>= 1) s += __shfl_xor_sync(0xffffffffu, s, o);
        float inv = 1.0f / (sqrtf(s) + 1e-6f);
        uint4 pk;
        pk.x = h2_as_u32(__floats2half2_rn(a0.x*inv, a0.y*inv));
        pk.y = h2_as_u32(__floats2half2_rn(a0.z*inv, a0.w*inv));
        pk.z = h2_as_u32(__floats2half2_rn(a1.x*inv, a1.y*inv));
        pk.w = h2_as_u32(__floats2half2_rn(a1.z*inv, a1.w*inv));
        ((uint4*)(h0 + base))[lane] = pk;
    }
}

// ---------------- downsample + fused normalization ----------------
__device__ __forceinline__ void resize_taps(int i, int n, int jj[4], float ww[4]) {
    float c = 2.0f * (float)i + 0.5f;
    float s = 0.0f;
#pragma unroll
    for (int t = 0; t < 4; t++) {
        int j = 2 * i - 1 + t;
        float w = 0.0f;
        if (j >= 0 && j < n) w = 1.0f - 0.5f * fabsf(c - (float)j);
        jj[t] = j < 0 ? 0 : (j > n - 1 ? n - 1 : j);
        ww[t] = w;
        s += w;
    }
    float inv = 1.0f / s;
#pragma unroll
    for (int t = 0; t < 4; t++) ww[t] *= inv;
}

__global__ void __launch_bounds__(256) downsample_norm_kernel(
    const float* __restrict__ in, float* __restrict__ outF,
    __half* __restrict__ outH, int Hi, int Wi) {
    int Ho = Hi >> 1, Wo = Wi >> 1;
    int p = blockIdx.x, b = blockIdx.y;
    int yo = p / Wo, xo = p % Wo;
    int c = threadIdx.x;
    int lane = c & 31, wrp = c >> 5;
    int jy[4], jx[4];
    float wy[4], wx[4];
    resize_taps(yo, Hi, jy, wy);
    resize_taps(xo, Wi, jx, wx);
    const float* ib = in + (size_t)b * Hi * Wi * NC;
    float acc = 0.0f;
#pragma unroll
    for (int a = 0; a < 4; a++) {
        float r = 0.0f;
#pragma unroll
        for (int t = 0; t < 4; t++)
            r += wx[t] * ib[((size_t)jy[a] * Wi + jx[t]) * NC + c];
        acc += wy[a] * r;
    }
    size_t oidx = (((size_t)b * Ho + yo) * Wo + xo) * NC + c;
    outF[oidx] = acc;
    // block-wide L2 norm over the 256 channels
    __shared__ float red[8];
    __shared__ float sinv;
    float s = acc * acc;
#pragma unroll
    for (int o = 16; o > 0; o >>= 1) s += __shfl_xor_sync(0xffffffffu, s, o);
    if (lane == 0) red[wrp] = s;
    __syncthreads();
    if (c == 0) {
        float t = 0.0f;
#pragma unroll
        for (int i = 0; i < 8; i++) t += red[i];
        sinv = 1.0f / (sqrtf(t) + 1e-6f);
    }
    __syncthreads();
    outH[oidx] = __float2half(acc * sinv);
}

// ---------------- Main: block = (cell, level), mma.sync GEMM per group ----
// Padded smem layout (16B aligned). A/B row stride 528B (= 33x16B, conflict-free).
#define SA_B   528
#define SM_A   0                         // 128 * 528 = 67584
#define SM_B   67584                     // 16 * 528 = 8448
#define SM_D   76032                     // 128 * 17 * 4 = 8704
#define SM_QPS 84736
#define SM_QX  84800
#define SM_QY  84864
#define SMEM_DYN 84992

__global__ void __launch_bounds__(256) corr_kernel(
    const float* __restrict__ coords2,
    const __half* __restrict__ h0,
    const __half* __restrict__ hA,
    float* __restrict__ out) {
    extern __shared__ __align__(16) char sal[];
    u32 sb = smem_u32(sal);

    int tid = threadIdx.x, lane = tid & 31, wid = tid >> 5;
    int bid = blockIdx.x;              // 0..511: cell id
    int l = blockIdx.y;                // level
    int b = bid >> 8;
    int cell = bid & 255;
    int cx = cell & 15, cy = cell >> 4;
    int start = g_binoff[bid], end = g_binoff[bid + 1];
    int nq = end - start;
    if (nq == 0) return;

    float* Dsm = (float*)(sal + SM_D);
    int*   qps = (int*)(sal + SM_QPS);
    float* qxs = (float*)(sal + SM_QX);
    float* qys = (float*)(sal + SM_QY);

    const int Wl = NW >> l, Hl = NH >> l;
    const float inv_scl = 1.0f / (float)(1 << l);
    const __half* fb;
    if (l == 0)      fb = h0 + (size_t)b * 64 * 64 * NC;
    else if (l == 1) fb = hA + ((size_t)OFF_L1 + (size_t)b * 32 * 32) * NC;
    else if (l == 2) fb = hA + ((size_t)OFF_L2 + (size_t)b * 16 * 16) * NC;
    else             fb = hA + ((size_t)OFF_L3 + (size_t)b * 8 * 8) * NC;
    // cell-static integer window union at this level
    int ixlo = (l == 0) ? cx*4 : (l == 1) ? cx*2 : (l == 2) ? cx : (cx >> 1);
    int iylo = (l == 0) ? cy*4 : (l == 1) ? cy*2 : (l == 2) ? cy : (cy >> 1);
    int span = (l == 0) ? 3 : (l == 1) ? 1 : 0;
    int ux0 = max(0, ixlo - 3), ux1 = min(Wl - 1, ixlo + span + 4);
    int uy0 = max(0, iylo - 3), uy1 = min(Hl - 1, iylo + span + 4);
    int uw = ux1 - ux0 + 1;
    int upix = uw * (uy1 - uy0 + 1);   // <= 121

    // ---- stage union window rows into padded A smem ----
    for (int r = wid; r < upix; r += 8) {
        int ry = r / uw, rx = r - ry * uw;
        int yy = uy0 + ry, xx = ux0 + rx;
        uint4 v = __ldg((const uint4*)(fb + ((size_t)yy * Wl + xx) * NC) + lane);
        *(uint4*)(sal + SM_A + r * SA_B + lane * 16) = v;
    }
    __syncthreads();

    int ngroups = (nq + 15) >> 4;
#pragma unroll 1
    for (int g = 0; g < ngroups; g++) {
        int gs = start + g * 16;
        int vcnt = min(16, end - gs);
        // ---- stage B: gather up to 16 feat1 rows via perm ----
        for (int qi = wid; qi < 16; qi += 8) {
            if (qi < vcnt) {
                int p = __ldg(&g_perm[gs + qi]);
                uint4 v = __ldg((const uint4*)(g_feat1h + (size_t)p * NC) + lane);
                *(uint4*)(sal + SM_B + qi * SA_B + lane * 16) = v;
            }
        }
        if (tid < 16 && tid < vcnt) {
            int p = g_perm[gs + tid];
            qps[tid] = p;
            qxs[tid] = __ldg(&coords2[(size_t)p * 2 + 0]);
            qys[tid] = __ldg(&coords2[(size_t)p * 2 + 1]);
        }
        __syncthreads();

        // ---- MMA: warp `wid` computes D rows [16*wid, 16*wid+16) x 16 queries ----
        {
            float c0[4] = {0.f, 0.f, 0.f, 0.f};
            float c1[4] = {0.f, 0.f, 0.f, 0.f};
            u32 a_base = sb + SM_A + (16 * wid + (lane & 15)) * SA_B + (lane >> 4) * 16;
            u32 b_base = sb + SM_B + (lane & 7) * SA_B + ((lane >> 3) & 1) * 16;
#pragma unroll
            for (int kc = 0; kc < 16; kc++) {
                u32 a0, a1, a2, a3, b0, b1, b2, b3;
                ldsm_x4(a0, a1, a2, a3, a_base + kc * 32);
                ldsm_x2(b0, b1, b_base + kc * 32);
                mma16816(c0, a0, a1, a2, a3, b0, b1);
                ldsm_x2(b2, b3, b_base + 8 * SA_B + kc * 32);
                mma16816(c1, a0, a1, a2, a3, b2, b3);
            }
            int row0 = 16 * wid + (lane >> 2);
            int col = 2 * (lane & 3);
            Dsm[row0 * 17 + col]           = c0[0];
            Dsm[row0 * 17 + col + 1]       = c0[1];
            Dsm[(row0 + 8) * 17 + col]     = c0[2];
            Dsm[(row0 + 8) * 17 + col + 1] = c0[3];
            Dsm[row0 * 17 + 8 + col]           = c1[0];
            Dsm[row0 * 17 + 8 + col + 1]       = c1[1];
            Dsm[(row0 + 8) * 17 + 8 + col]     = c1[2];
            Dsm[(row0 + 8) * 17 + 8 + col + 1] = c1[3];
        }
        __syncthreads();

        // ---- blend: thread t -> query t/16, outputs k = t%16 (+16,+32) ----
        int qi = tid >> 4, j = tid & 15;
        if (qi < vcnt) {
            float bx = qxs[qi] * inv_scl;
            float by = qys[qi] * inv_scl;
            int p = qps[qi];
            for (int k = j; k < NK; k += 16) {
                int dy = k / 7 - 3, dx = k % 7 - 3;
                float xk = fminf(fmaxf(bx + (float)dx, 0.0f), (float)(Wl - 1));
                float yk = fminf(fmaxf(by + (float)dy, 0.0f), (float)(Hl - 1));
                float fx = floorf(xk), fy = floorf(yk);
                float xh = fminf(fx + 1.0f, (float)(Wl - 1));
                float yh = fminf(fy + 1.0f, (float)(Hl - 1));
                float wx1 = xk - fx, wx0 = xh - xk;
                float wy1 = yk - fy, wy0 = yh - yk;
                int px0 = (int)fx - ux0, px1 = (int)xh - ux0;
                int py0 = (int)fy - uy0, py1 = (int)yh - uy0;
                float val = wx0 * wy0 * Dsm[(py0 * uw + px0) * 17 + qi] +
                            wx0 * wy1 * Dsm[(py1 * uw + px0) * 17 + qi] +
                            wx1 * wy0 * Dsm[(py0 * uw + px1) * 17 + qi] +
                            wx1 * wy1 * Dsm[(py1 * uw + px1) * 17 + qi];
                out[(size_t)p * (NLEV * NK) + l * NK + k] = val;
            }
        }
        __syncthreads();   // before next group's B staging
    }
}

extern "C" void kernel_launch(void* const* d_in, const int* in_sizes, int n_in,
                              void* d_out, int out_size) {
    const float* fmap1   = (const float*)d_in[0];
    const float* fmap2   = (const float*)d_in[1];
    const float* coords1 = (const float*)d_in[2];
    const float* coords2 = (const float*)d_in[3];
    float* out = (float*)d_out;

    float* pyrA;
    __half *h0, *hA;
    cudaGetSymbolAddress((void**)&pyrA, g_pyrA);
    cudaGetSymbolAddress((void**)&h0, g_h0);
    cudaGetSymbolAddress((void**)&hA, g_hA);

    float* pyr1 = pyrA + (size_t)OFF_L1 * NC;
    float* pyr2 = pyrA + (size_t)OFF_L2 * NC;
    float* pyr3 = pyrA + (size_t)OFF_L3 * NC;
    __half* h1 = hA + (size_t)OFF_L1 * NC;
    __half* h2 = hA + (size_t)OFF_L2 * NC;
    __half* h3 = hA + (size_t)OFF_L3 * NC;

    cudaFuncSetAttribute(corr_kernel, cudaFuncAttributeMaxDynamicSharedMemorySize, SMEM_DYN);

    // launches: 0 sort, 1 feat1+norm0, 2 ds1, 3 ds2, 4 ds3, 5 corr (-> ncu -s 5 profiles corr)
    sort_kernel<<<1, 1024>>>(coords2);
    feat1_norm0_kernel<<<NB * NQ / 8 + NB * 64 * 64 / 8, 256>>>(fmap1, coords1, fmap2, h0);
    downsample_norm_kernel<<<dim3(32 * 32, NB), 256>>>(fmap2, pyr1, h1, 64, 64);
    downsample_norm_kernel<<<dim3(16 * 16, NB), 256>>>(pyr1, pyr2, h2, 32, 32);
    downsample_norm_kernel<<<dim3(8 * 8, NB), 256>>>(pyr2, pyr3, h3, 16, 16);
    corr_kernel<<<dim3(NB * NBINS, NLEV), 256, SMEM_DYN>>>(coords2, h0, hA, out);
}

// round 14
// speedup vs baseline: 1.8259x; 1.2606x over previous
#include <cuda_runtime.h>
#include <cuda_fp16.h>
#include <math.h>
#include <stdint.h>

typedef unsigned int       u32;
typedef unsigned long long u64;

#define NB 2
#define NH 64
#define NW 64
#define NC 256
#define NQ 4096
#define NK 49
#define NLEV 4
#define NBINS 256

__device__ float  g_pyr1[NB*32*32*NC];
__device__ __half g_h0[NB*64*64*NC];
__device__ __half g_hA[NB*(32*32 + 16*16 + 8*8)*NC];
__device__ int    g_perm[NB*NQ];       // sorted slot -> packed query index
__device__ int    g_binoff[NB*NBINS + 1];
__device__ __half g_feat1h[NB*NQ*NC];  // normalized feat1, NATURAL (p) order

#define OFF_L1 0
#define OFF_L2 (NB * 32 * 32)
#define OFF_L3 (NB * (32*32 + 16*16))

// ---------------- helpers ----------------
__device__ __forceinline__ u32 h2_as_u32(__half2 h) {
    return *reinterpret_cast<u32*>(&h);
}
__device__ __forceinline__ u32 smem_u32(const void* p) {
    u32 a;
    asm("{ .reg .u64 t; cvta.to.shared.u64 t, %1; cvt.u32.u64 %0, t; }" : "=r"(a) : "l"(p));
    return a;
}
__device__ __forceinline__ void cp16(u32 dst, const void* src) {
    asm volatile("cp.async.cg.shared.global [%0], [%1], 16;" :: "r"(dst), "l"(src));
}
#define CP_COMMIT() asm volatile("cp.async.commit_group;" ::: "memory")
#define CP_WAIT0()  asm volatile("cp.async.wait_group 0;" ::: "memory")

__device__ __forceinline__ void ldsm_x4(u32& r0, u32& r1, u32& r2, u32& r3, u32 a) {
    asm volatile("ldmatrix.sync.aligned.m8n8.x4.shared.b16 {%0,%1,%2,%3}, [%4];"
                 : "=r"(r0), "=r"(r1), "=r"(r2), "=r"(r3) : "r"(a));
}
__device__ __forceinline__ void ldsm_x2(u32& r0, u32& r1, u32 a) {
    asm volatile("ldmatrix.sync.aligned.m8n8.x2.shared.b16 {%0,%1}, [%2];"
                 : "=r"(r0), "=r"(r1) : "r"(a));
}
__device__ __forceinline__ void mma16816(float* c, u32 a0, u32 a1, u32 a2, u32 a3,
                                         u32 b0, u32 b1) {
    asm volatile("mma.sync.aligned.m16n8k16.row.col.f32.f16.f16.f32 "
                 "{%0,%1,%2,%3}, {%4,%5,%6,%7}, {%8,%9}, {%0,%1,%2,%3};"
                 : "+f"(c[0]), "+f"(c[1]), "+f"(c[2]), "+f"(c[3])
                 : "r"(a0), "r"(a1), "r"(a2), "r"(a3), "r"(b0), "r"(b1));
}

// jax.image.resize(bilinear, antialias) 2x-down taps; ww=0 for out-of-range raw j.
__device__ __forceinline__ void resize_taps(int i, int n, int jj[4], float ww[4]) {
    float c = 2.0f * (float)i + 0.5f;
    float s = 0.0f;
#pragma unroll
    for (int t = 0; t < 4; t++) {
        int j = 2 * i - 1 + t;
        float w = 0.0f;
        if (j >= 0 && j < n) w = 1.0f - 0.5f * fabsf(c - (float)j);
        jj[t] = j < 0 ? 0 : (j > n - 1 ? n - 1 : j);
        ww[t] = w;
        s += w;
    }
    float inv = 1.0f / s;
#pragma unroll
    for (int t = 0; t < 4; t++) ww[t] *= inv;
}

// ---------------- mega kernel: sort | feat1 | norm0 | ds1 ----------------
// grid 4097 x 256: block 0 = sort; 1..1024 feat1; 1025..2048 norm0; 2049..4096 ds1.
__global__ void __launch_bounds__(256) mega_kernel(
    const float* __restrict__ coords2,
    const float* __restrict__ fmap1, const float* __restrict__ coords1,
    const float* __restrict__ fmap2, __half* __restrict__ h0,
    float* __restrict__ pyr1, __half* __restrict__ h1) {
    int tid = threadIdx.x, lane = tid & 31, wrp = tid >> 5;

    if (blockIdx.x == 0) {
        // ---- counting sort of 8192 queries by level-0 4x4 cell, 256 threads ----
        __shared__ int cnt[NB*NBINS];
        __shared__ int coff[NB*NBINS];
        __shared__ int wsum[8], wpre[8];
        cnt[tid] = 0; cnt[tid + 256] = 0;
        __syncthreads();
        int bins[32];
#pragma unroll
        for (int k = 0; k < 32; k++) {
            int i = k * 256 + tid;
            int b = i >> 12;
            float qx = coords2[(size_t)i * 2 + 0];
            float qy = coords2[(size_t)i * 2 + 1];
            int ix = min(max((int)floorf(qx), 0), 63);
            int iy = min(max((int)floorf(qy), 0), 63);
            bins[k] = b * NBINS + ((iy >> 2) << 4) + (ix >> 2);
            atomicAdd(&cnt[bins[k]], 1);
        }
        __syncthreads();
        int local = cnt[2 * tid] + cnt[2 * tid + 1];
        int li = local;
#pragma unroll
        for (int o = 1; o < 32; o <<= 1) {
            int v = __shfl_up_sync(0xffffffffu, li, o);
            if (lane >= o) li += v;
        }
        if (lane == 31) wsum[wrp] = li;
        __syncthreads();
        if (tid == 0) {
            int r = 0;
#pragma unroll
            for (int w = 0; w < 8; w++) { wpre[w] = r; r += wsum[w]; }
        }
        __syncthreads();
        int ep = li - local + wpre[wrp];
        coff[2 * tid]     = ep;
        coff[2 * tid + 1] = ep + cnt[2 * tid];
        g_binoff[2 * tid]     = ep;
        g_binoff[2 * tid + 1] = ep + cnt[2 * tid];
        if (tid == 0) g_binoff[NB*NBINS] = NB*NQ;
        __syncthreads();
#pragma unroll
        for (int k = 0; k < 32; k++) {
            int i = k * 256 + tid;
            int slot = atomicAdd(&coff[bins[k]], 1);
            g_perm[slot] = i;
        }
    } else if (blockIdx.x <= 1024) {
        // ---- feat1: warp per query, natural index ----
        int p = (blockIdx.x - 1) * 8 + wrp;
        int b = p >> 12;
        float cx = __ldg(&coords1[(size_t)p * 2 + 0]);
        float cy = __ldg(&coords1[(size_t)p * 2 + 1]);
        int fx0 = (int)floorf(cx), fy0 = (int)floorf(cy);
        int x0 = min(max(fx0, 0), NW - 1), x1 = min(max(fx0 + 1, 0), NW - 1);
        int y0 = min(max(fy0, 0), NH - 1), y1 = min(max(fy0 + 1, 0), NH - 1);
        float wa = ((float)x1 - cx) * ((float)y1 - cy);
        float wb = ((float)x1 - cx) * (cy - (float)y0);
        float wc = (cx - (float)x0) * ((float)y1 - cy);
        float wd = (cx - (float)x0) * (cy - (float)y0);
        const float* fb1 = fmap1 + (size_t)b * NH * NW * NC;
        int c0 = lane * 8;
        const float4* pa = (const float4*)(fb1 + ((size_t)y0 * NW + x0) * NC + c0);
        const float4* pb = (const float4*)(fb1 + ((size_t)y1 * NW + x0) * NC + c0);
        const float4* pc = (const float4*)(fb1 + ((size_t)y0 * NW + x1) * NC + c0);
        const float4* pd = (const float4*)(fb1 + ((size_t)y1 * NW + x1) * NC + c0);
        float v[8];
#pragma unroll
        for (int h = 0; h < 2; h++) {
            float4 A = __ldcg(pa + h), Bv = __ldcg(pb + h), Cv = __ldcg(pc + h), Dv = __ldcg(pd + h);
            v[h*4+0] = wa*A.x + wb*Bv.x + wc*Cv.x + wd*Dv.x;
            v[h*4+1] = wa*A.y + wb*Bv.y + wc*Cv.y + wd*Dv.y;
            v[h*4+2] = wa*A.z + wb*Bv.z + wc*Cv.z + wd*Dv.z;
            v[h*4+3] = wa*A.w + wb*Bv.w + wc*Cv.w + wd*Dv.w;
        }
        float s2 = 0.0f;
#pragma unroll
        for (int j = 0; j < 8; j++) s2 += v[j] * v[j];
#pragma unroll
        for (int o = 16; o > 0; o >>= 1) s2 += __shfl_xor_sync(0xffffffffu, s2, o);
        float inv = 1.0f / (sqrtf(s2) + 1e-6f);
        uint4 pk;
        pk.x = h2_as_u32(__floats2half2_rn(v[0]*inv, v[1]*inv));
        pk.y = h2_as_u32(__floats2half2_rn(v[2]*inv, v[3]*inv));
        pk.z = h2_as_u32(__floats2half2_rn(v[4]*inv, v[5]*inv));
        pk.w = h2_as_u32(__floats2half2_rn(v[6]*inv, v[7]*inv));
        ((uint4*)(g_feat1h + (size_t)p * NC))[lane] = pk;
    } else if (blockIdx.x <= 2048) {
        // ---- normalize level 0: warp per pixel ----
        int p = (blockIdx.x - 1025) * 8 + wrp;
        size_t base = (size_t)p * NC;
        const float4* ip = (const float4*)(fmap2 + base);
        float4 a0 = ip[lane * 2];
        float4 a1 = ip[lane * 2 + 1];
        float s = a0.x*a0.x + a0.y*a0.y + a0.z*a0.z + a0.w*a0.w +
                  a1.x*a1.x + a1.y*a1.y + a1.z*a1.z + a1.w*a1.w;
#pragma unroll
        for (int o = 16; o > 0; o >>= 1) s += __shfl_xor_sync(0xffffffffu, s, o);
        float inv = 1.0f / (sqrtf(s) + 1e-6f);
        uint4 pk;
        pk.x = h2_as_u32(__floats2half2_rn(a0.x*inv, a0.y*inv));
        pk.y = h2_as_u32(__floats2half2_rn(a0.z*inv, a0.w*inv));
        pk.z = h2_as_u32(__floats2half2_rn(a1.x*inv, a1.y*inv));
        pk.w = h2_as_u32(__floats2half2_rn(a1.z*inv, a1.w*inv));
        ((uint4*)(h0 + base))[lane] = pk;
    } else {
        // ---- ds1: L0 -> L1, fp32 + normalized fp16, block per output pixel ----
        int idx = blockIdx.x - 2049;         // 0..2047
        int b = idx >> 10, p = idx & 1023;
        int yo = p >> 5, xo = p & 31;
        int c = tid;
        int jy[4], jx[4];
        float wy[4], wx[4];
        resize_taps(yo, 64, jy, wy);
        resize_taps(xo, 64, jx, wx);
        const float* ib = fmap2 + (size_t)b * 64 * 64 * NC;
        float acc = 0.0f;
#pragma unroll
        for (int a = 0; a < 4; a++) {
            float r = 0.0f;
#pragma unroll
            for (int t = 0; t < 4; t++)
                r += wx[t] * ib[((size_t)jy[a] * 64 + jx[t]) * NC + c];
            acc += wy[a] * r;
        }
        size_t oidx = (((size_t)b * 32 + yo) * 32 + xo) * NC + c;
        pyr1[oidx] = acc;
        __shared__ float red[8];
        __shared__ float sinv;
        float s = acc * acc;
#pragma unroll
        for (int o = 16; o > 0; o >>= 1) s += __shfl_xor_sync(0xffffffffu, s, o);
        if (lane == 0) red[wrp] = s;
        __syncthreads();
        if (c == 0) {
            float t = 0.0f;
#pragma unroll
            for (int i = 0; i < 8; i++) t += red[i];
            sinv = 1.0f / (sqrtf(t) + 1e-6f);
        }
        __syncthreads();
        h1[oidx] = __float2half(acc * sinv);
    }
}

// ---------------- ds23: L2 (4-tap) and L3 (composed 10x10) from L1 ----------------
// grid 640: blocks 0..511 -> L2 pixels, 512..639 -> L3 pixels.
__global__ void __launch_bounds__(256) ds23_kernel(
    const float* __restrict__ pyr1, __half* __restrict__ h2, __half* __restrict__ h3) {
    int tid = threadIdx.x, lane = tid & 31, wrp = tid >> 5;
    __shared__ float red[8];
    __shared__ float sinv;
    float acc = 0.0f;
    __half* outp;
    size_t oidx;

    if (blockIdx.x < 512) {
        int idx = blockIdx.x;
        int b = idx >> 8, p = idx & 255;
        int yo = p >> 4, xo = p & 15;
        int jy[4], jx[4];
        float wy[4], wx[4];
        resize_taps(yo, 32, jy, wy);
        resize_taps(xo, 32, jx, wx);
        const float* ib = pyr1 + (size_t)b * 32 * 32 * NC;
#pragma unroll
        for (int a = 0; a < 4; a++) {
            float r = 0.0f;
#pragma unroll
            for (int t = 0; t < 4; t++)
                r += wx[t] * ib[((size_t)jy[a] * 32 + jx[t]) * NC + tid];
            acc += wy[a] * r;
        }
        outp = h2;
        oidx = (((size_t)b * 16 + yo) * 16 + xo) * NC + tid;
    } else {
        int idx = blockIdx.x - 512;          // 0..127
        int b = idx >> 6, p = idx & 63;
        int yo = p >> 3, xo = p & 7;
        // composed weights over L1: base index 4*o-3, 10 taps
        float cwy[10], cwx[10];
#pragma unroll
        for (int u = 0; u < 10; u++) { cwy[u] = 0.0f; cwx[u] = 0.0f; }
        {
            int jj3[4], jj2[4];
            float w3[4], w2[4];
            resize_taps(yo, 16, jj3, w3);
#pragma unroll
            for (int t = 0; t < 4; t++) {
                int j = 2 * yo - 1 + t;         // raw L2 index (w3[t]=0 if OOR)
                resize_taps(j, 32, jj2, w2);    // raw inner: 2j-1+s (w2=0 if OOR)
#pragma unroll
                for (int s = 0; s < 4; s++) cwy[2 * t + s] += w3[t] * w2[s];
            }
            resize_taps(xo, 16, jj3, w3);
#pragma unroll
            for (int t = 0; t < 4; t++) {
                int j = 2 * xo - 1 + t;
                resize_taps(j, 32, jj2, w2);
#pragma unroll
                for (int s = 0; s < 4; s++) cwx[2 * t + s] += w3[t] * w2[s];
            }
        }
        const float* ib = pyr1 + (size_t)b * 32 * 32 * NC;
#pragma unroll
        for (int a = 0; a < 10; a++) {
            if (cwy[a] == 0.0f) continue;
            int ya = min(max(4 * yo - 3 + a, 0), 31);
            float r = 0.0f;
#pragma unroll
            for (int bb = 0; bb < 10; bb++) {
                if (cwx[bb] == 0.0f) continue;
                int xb = min(max(4 * xo - 3 + bb, 0), 31);
                r += cwx[bb] * ib[((size_t)ya * 32 + xb) * NC + tid];
            }
            acc += cwy[a] * r;
        }
        outp = h3;
        oidx = (((size_t)b * 8 + yo) * 8 + xo) * NC + tid;
    }
    float s = acc * acc;
#pragma unroll
    for (int o = 16; o > 0; o >>= 1) s += __shfl_xor_sync(0xffffffffu, s, o);
    if (lane == 0) red[wrp] = s;
    __syncthreads();
    if (tid == 0) {
        float t = 0.0f;
#pragma unroll
        for (int i = 0; i < 8; i++) t += red[i];
        sinv = 1.0f / (sqrtf(t) + 1e-6f);
    }
    __syncthreads();
    outp[oidx] = __float2half(acc * sinv);
}

// ---------------- Main: block = (cell, level), cp.async staging + mma.sync ----------------
#define SA_B   528
#define SM_A   0                         // 128 * 528 = 67584
#define SM_B   67584                     // 16 * 528 = 8448
#define SM_D   76032                     // 128 * 17 * 4 = 8704
#define SM_QPS 84736
#define SM_QX  84800
#define SM_QY  84864
#define SMEM_DYN 84992

__global__ void __launch_bounds__(256) corr_kernel(
    const float* __restrict__ coords2,
    const __half* __restrict__ h0,
    const __half* __restrict__ hA,
    float* __restrict__ out) {
    extern __shared__ __align__(16) char sal[];
    u32 sb = smem_u32(sal);

    int tid = threadIdx.x, lane = tid & 31, wid = tid >> 5;
    int bid = blockIdx.x;              // 0..511: cell id
    int l = blockIdx.y;                // level
    int b = bid >> 8;
    int cell = bid & 255;
    int cx = cell & 15, cy = cell >> 4;
    int start = g_binoff[bid], end = g_binoff[bid + 1];
    int nq = end - start;
    if (nq == 0) return;

    float* Dsm = (float*)(sal + SM_D);
    int*   qps = (int*)(sal + SM_QPS);
    float* qxs = (float*)(sal + SM_QX);
    float* qys = (float*)(sal + SM_QY);

    const int Wl = NW >> l, Hl = NH >> l;
    const float inv_scl = 1.0f / (float)(1 << l);
    const __half* fb;
    if (l == 0)      fb = h0 + (size_t)b * 64 * 64 * NC;
    else if (l == 1) fb = hA + ((size_t)OFF_L1 + (size_t)b * 32 * 32) * NC;
    else if (l == 2) fb = hA + ((size_t)OFF_L2 + (size_t)b * 16 * 16) * NC;
    else             fb = hA + ((size_t)OFF_L3 + (size_t)b * 8 * 8) * NC;
    int ixlo = (l == 0) ? cx*4 : (l == 1) ? cx*2 : (l == 2) ? cx : (cx >> 1);
    int iylo = (l == 0) ? cy*4 : (l == 1) ? cy*2 : (l == 2) ? cy : (cy >> 1);
    int span = (l == 0) ? 3 : (l == 1) ? 1 : 0;
    int ux0 = max(0, ixlo - 3), ux1 = min(Wl - 1, ixlo + span + 4);
    int uy0 = max(0, iylo - 3), uy1 = min(Hl - 1, iylo + span + 4);
    int uw = ux1 - ux0 + 1;
    int upix = uw * (uy1 - uy0 + 1);   // <= 121

    // ---- stage union window into padded A smem via cp.async (fully pipelined) ----
    for (int r = wid; r < upix; r += 8) {
        int ry = r / uw, rx = r - ry * uw;
        int yy = uy0 + ry, xx = ux0 + rx;
        cp16(sb + SM_A + r * SA_B + lane * 16,
             (const char*)(fb + ((size_t)yy * Wl + xx) * NC) + lane * 16);
    }
    CP_COMMIT();
    CP_WAIT0();
    __syncthreads();

    int ngroups = (nq + 15) >> 4;
#pragma unroll 1
    for (int g = 0; g < ngroups; g++) {
        int gs = start + g * 16;
        int vcnt = min(16, end - gs);
        // ---- stage B: gather up to 16 feat1 rows via perm (cp.async) ----
        for (int qi = wid; qi < 16; qi += 8) {
            if (qi < vcnt) {
                int p = __ldg(&g_perm[gs + qi]);
                cp16(sb + SM_B + qi * SA_B + lane * 16,
                     (const char*)(g_feat1h + (size_t)p * NC) + lane * 16);
            }
        }
        CP_COMMIT();
        if (tid < 16 && tid < vcnt) {
            int p = g_perm[gs + tid];
            qps[tid] = p;
            qxs[tid] = __ldg(&coords2[(size_t)p * 2 + 0]);
            qys[tid] = __ldg(&coords2[(size_t)p * 2 + 1]);
        }
        CP_WAIT0();
        __syncthreads();

        // ---- MMA: warp `wid` computes D rows [16*wid, 16*wid+16) x 16 queries ----
        {
            float c0[4] = {0.f, 0.f, 0.f, 0.f};
            float c1[4] = {0.f, 0.f, 0.f, 0.f};
            u32 a_base = sb + SM_A + (16 * wid + (lane & 15)) * SA_B + (lane >> 4) * 16;
            u32 b_base = sb + SM_B + (lane & 7) * SA_B + ((lane >> 3) & 1) * 16;
#pragma unroll
            for (int kc = 0; kc < 16; kc++) {
                u32 a0, a1, a2, a3, b0, b1, b2, b3;
                ldsm_x4(a0, a1, a2, a3, a_base + kc * 32);
                ldsm_x2(b0, b1, b_base + kc * 32);
                mma16816(c0, a0, a1, a2, a3, b0, b1);
                ldsm_x2(b2, b3, b_base + 8 * SA_B + kc * 32);
                mma16816(c1, a0, a1, a2, a3, b2, b3);
            }
            int row0 = 16 * wid + (lane >> 2);
            int col = 2 * (lane & 3);
            Dsm[row0 * 17 + col]           = c0[0];
            Dsm[row0 * 17 + col + 1]       = c0[1];
            Dsm[(row0 + 8) * 17 + col]     = c0[2];
            Dsm[(row0 + 8) * 17 + col + 1] = c0[3];
            Dsm[row0 * 17 + 8 + col]           = c1[0];
            Dsm[row0 * 17 + 8 + col + 1]       = c1[1];
            Dsm[(row0 + 8) * 17 + 8 + col]     = c1[2];
            Dsm[(row0 + 8) * 17 + 8 + col + 1] = c1[3];
        }
        __syncthreads();

        // ---- blend ----
        int qi = tid >> 4, j = tid & 15;
        if (qi < vcnt) {
            float bx = qxs[qi] * inv_scl;
            float by = qys[qi] * inv_scl;
            int p = qps[qi];
            for (int k = j; k < NK; k += 16) {
                int dy = k / 7 - 3, dx = k % 7 - 3;
                float xk = fminf(fmaxf(bx + (float)dx, 0.0f), (float)(Wl - 1));
                float yk = fminf(fmaxf(by + (float)dy, 0.0f), (float)(Hl - 1));
                float fx = floorf(xk), fy = floorf(yk);
                float xh = fminf(fx + 1.0f, (float)(Wl - 1));
                float yh = fminf(fy + 1.0f, (float)(Hl - 1));
                float wx1 = xk - fx, wx0 = xh - xk;
                float wy1 = yk - fy, wy0 = yh - yk;
                int px0 = (int)fx - ux0, px1 = (int)xh - ux0;
                int py0 = (int)fy - uy0, py1 = (int)yh - uy0;
                float val = wx0 * wy0 * Dsm[(py0 * uw + px0) * 17 + qi] +
                            wx0 * wy1 * Dsm[(py1 * uw + px0) * 17 + qi] +
                            wx1 * wy0 * Dsm[(py0 * uw + px1) * 17 + qi] +
                            wx1 * wy1 * Dsm[(py1 * uw + px1) * 17 + qi];
                out[(size_t)p * (NLEV * NK) + l * NK + k] = val;
            }
        }
        __syncthreads();
    }
}

extern "C" void kernel_launch(void* const* d_in, const int* in_sizes, int n_in,
                              void* d_out, int out_size) {
    const float* fmap1   = (const float*)d_in[0];
    const float* fmap2   = (const float*)d_in[1];
    const float* coords1 = (const float*)d_in[2];
    const float* coords2 = (const float*)d_in[3];
    float* out = (float*)d_out;

    float* pyr1;
    __half *h0, *hA;
    cudaGetSymbolAddress((void**)&pyr1, g_pyr1);
    cudaGetSymbolAddress((void**)&h0, g_h0);
    cudaGetSymbolAddress((void**)&hA, g_hA);

    __half* h1 = hA + (size_t)OFF_L1 * NC;
    __half* h2 = hA + (size_t)OFF_L2 * NC;
    __half* h3 = hA + (size_t)OFF_L3 * NC;

    cudaFuncSetAttribute(corr_kernel, cudaFuncAttributeMaxDynamicSharedMemorySize, SMEM_DYN);

    mega_kernel<<<4097, 256>>>(coords2, fmap1, coords1, fmap2, h0, pyr1, h1);
    ds23_kernel<<<640, 256>>>(pyr1, h2, h3);
    corr_kernel<<<dim3(NB * NBINS, NLEV), 256, SMEM_DYN>>>(coords2, h0, hA, out);
}